// round 9
// baseline (speedup 1.0000x reference)
#include <cuda_runtime.h>
#include <cuda_fp16.h>
#include <cstdint>

// Problem constants (dataset-fixed)
#define D 128
#define BATCH 2
#define MAXN 50000
#define MAXBN (BATCH * MAXN)
#define MAXE 800000
#define LN_EPS 1e-5f

// Scratch buffers
__device__ __align__(16) __half g_mh[MAXBN * D];  // h @ W_msg^T, fp16 (25.6MB)
__device__ __align__(16) float g_agg[MAXBN * D];  // gathered aggregate
__device__ __align__(16) float g_Wm[D * D];       // W_msg, tf32-rounded
__device__ __align__(16) float g_Wu[D * 2 * D];   // W_upd, tf32-rounded

// CSR-by-target scratch
__device__ int g_cnt[MAXN];
__device__ int g_excl[MAXN];
__device__ int g_blksum[256];
__device__ int g_rowptr[MAXN + 1];
__device__ int g_cursor[MAXN];
__device__ int g_perm[MAXE];

#define SCAN_BLK 256

// ---- tf32 round-to-nearest (RNA via bit trick) -----------------------------
__device__ __forceinline__ float tf32_rn(float x) {
    uint32_t b = __float_as_uint(x);
    b = (b + 0x00001000u) & 0xFFFFE000u;
    return __uint_as_float(b);
}

// ---- warp-level TF32 MMA (sm_80+ baseline PTX; maps to HMMA) ---------------
__device__ __forceinline__ void mma_tf32(float c[4],
                                         uint32_t a0, uint32_t a1,
                                         uint32_t a2, uint32_t a3,
                                         uint32_t b0, uint32_t b1) {
    asm volatile(
        "mma.sync.aligned.m16n8k8.row.col.f32.tf32.tf32.f32 "
        "{%0,%1,%2,%3}, {%4,%5,%6,%7}, {%8,%9}, {%0,%1,%2,%3};"
        : "+f"(c[0]), "+f"(c[1]), "+f"(c[2]), "+f"(c[3])
        : "r"(a0), "r"(a1), "r"(a2), "r"(a3), "r"(b0), "r"(b1));
}

// smem: A tile [128m][132k-packed] + B tile [128n][132k-packed] floats
// packed layout within a row: word for logical k sits at
//   pos(k) = (k>>3)*8 + (k&3)*2 + ((k>>2)&1)
// so the (k, k+4) tf32 fragment pair is one aligned 8-byte LDS.
#define TS 132
#define TS2 66                      // TS/2, for uint2 indexing
#define SM_A_OFF 0
#define SM_B_OFF (128 * TS)
#define SMEM_MMA ((2 * 128 * TS) * sizeof(float))   // 135168 B

// ============================================================================
// prep: zero counters + tf32-round weights
// ============================================================================
__global__ void prep_kernel(const float* __restrict__ Wm,
                            const float* __restrict__ Wu, int N) {
    int i = blockIdx.x * blockDim.x + threadIdx.x;  // >= 50176 threads
    if (i < N) g_cnt[i] = 0;
    if (i < 256) g_blksum[i] = 0;
    if (i < D * D) g_Wm[i] = tf32_rn(Wm[i]);
    if (i < 2 * D * D) g_Wu[i] = tf32_rn(Wu[i]);
}

// ============================================================================
// CSR build (histogram -> scan1 -> merged scan23 -> permutation scatter)
// ============================================================================
__global__ void hist_kernel(const int* __restrict__ tgt, int E) {
    int i = blockIdx.x * blockDim.x + threadIdx.x;
    if (i < E) atomicAdd(&g_cnt[tgt[i]], 1);
}

__global__ void scan1_kernel(int N) {
    __shared__ int s[SCAN_BLK];
    int t = threadIdx.x;
    int i = blockIdx.x * SCAN_BLK + t;
    int v = (i < N) ? g_cnt[i] : 0;
    s[t] = v; __syncthreads();
    #pragma unroll
    for (int off = 1; off < SCAN_BLK; off <<= 1) {
        int x = (t >= off) ? s[t - off] : 0;
        __syncthreads();
        s[t] += x; __syncthreads();
    }
    if (i < N) g_excl[i] = s[t] - v;
    if (t == SCAN_BLK - 1) g_blksum[blockIdx.x] = s[t];
}

__global__ void scan23_kernel(int N, int E) {
    __shared__ int s[SCAN_BLK];
    int t = threadIdx.x;
    int b = blockIdx.x;
    s[t] = (t < b) ? g_blksum[t] : 0;
    __syncthreads();
    #pragma unroll
    for (int off = SCAN_BLK / 2; off > 0; off >>= 1) {
        if (t < off) s[t] += s[t + off];
        __syncthreads();
    }
    int offset = s[0];
    int i = b * SCAN_BLK + t;
    if (i < N) {
        int rp = g_excl[i] + offset;
        g_rowptr[i] = rp;
        g_cursor[i] = rp;
    }
    if (b == 0 && t == 0) g_rowptr[N] = E;
}

__global__ void scatter_perm_kernel(const int* __restrict__ tgt, int E) {
    int i = blockIdx.x * blockDim.x + threadIdx.x;
    if (i < E) {
        int pos = atomicAdd(&g_cursor[tgt[i]], 1);
        g_perm[pos] = i;
    }
}

// ============================================================================
// Gather: one warp per target node, both batches, no atomics.
// m rows now fp16: per edge per batch a lane reads 4 cols = 8B (uint2/half2x2).
// ============================================================================
__global__ __launch_bounds__(256) void gather_kernel(
    const float* __restrict__ rel_emb,
    const int* __restrict__ src, const int* __restrict__ rel, int N)
{
    int w = blockIdx.x * 8 + (threadIdx.x >> 5);
    int lane = threadIdx.x & 31;
    if (w >= N) return;

    int beg = g_rowptr[w];
    int end = g_rowptr[w + 1];

    float4 a0 = make_float4(0.f, 0.f, 0.f, 0.f);
    float4 a1 = make_float4(0.f, 0.f, 0.f, 0.f);

    for (int chunk = beg; chunk < end; chunk += 32) {
        int myE = chunk + lane;
        int ms = 0, mr = 0;
        if (myE < end) {
            int id = g_perm[myE];
            ms = __ldg(&src[id]);
            mr = __ldg(&rel[id]);
        }
        int cnt = min(32, end - chunk);
        #pragma unroll 4
        for (int j = 0; j < cnt; j++) {
            int s = __shfl_sync(0xFFFFFFFFu, ms, j);
            int r = __shfl_sync(0xFFFFFFFFu, mr, j);
            float4 rv = *(const float4*)&rel_emb[r * D + lane * 4];
            const __half2* p0 = (const __half2*)&g_mh[(long)s * D + lane * 4];
            const __half2* p1 = (const __half2*)&g_mh[((long)N + s) * D + lane * 4];
            float2 u00 = __half22float2(p0[0]);
            float2 u01 = __half22float2(p0[1]);
            float2 u10 = __half22float2(p1[0]);
            float2 u11 = __half22float2(p1[1]);
            a0.x += u00.x * rv.x; a0.y += u00.y * rv.y;
            a0.z += u01.x * rv.z; a0.w += u01.y * rv.w;
            a1.x += u10.x * rv.x; a1.y += u10.y * rv.y;
            a1.z += u11.x * rv.z; a1.w += u11.y * rv.w;
        }
    }

    *(float4*)&g_agg[(long)w * D + lane * 4] = a0;
    *(float4*)&g_agg[((long)N + w) * D + lane * 4] = a1;
}

// ============================================================================
// Tile loaders (packed k-pair layout)
// ============================================================================
__device__ __forceinline__ void load_a_tile(float* As, const float* __restrict__ X,
                                            int ldx, int row0, int limit, int tid) {
    #pragma unroll
    for (int it = tid; it < 2048; it += 256) {       // 128 rows x 16 ksteps
        int m = it >> 4;
        int ks = it & 15;
        int row = row0 + m;
        float4 lo = make_float4(0.f, 0.f, 0.f, 0.f);
        float4 hi = make_float4(0.f, 0.f, 0.f, 0.f);
        if (row < limit) {
            lo = *(const float4*)&X[(long)row * ldx + ks * 8];
            hi = *(const float4*)&X[(long)row * ldx + ks * 8 + 4];
        }
        float4 p0 = make_float4(tf32_rn(lo.x), tf32_rn(hi.x),
                                tf32_rn(lo.y), tf32_rn(hi.y));
        float4 p1 = make_float4(tf32_rn(lo.z), tf32_rn(hi.z),
                                tf32_rn(lo.w), tf32_rn(hi.w));
        *(float4*)&As[m * TS + ks * 8]     = p0;
        *(float4*)&As[m * TS + ks * 8 + 4] = p1;
    }
}

__device__ __forceinline__ void load_b_tile(float* Bs, const float* __restrict__ W,
                                            int ldw, int koff, int tid) {
    #pragma unroll
    for (int it = tid; it < 2048; it += 256) {
        int n = it >> 4;
        int ks = it & 15;
        float4 lo = *(const float4*)&W[(long)n * ldw + koff + ks * 8];
        float4 hi = *(const float4*)&W[(long)n * ldw + koff + ks * 8 + 4];
        *(float4*)&Bs[n * TS + ks * 8]     = make_float4(lo.x, hi.x, lo.y, hi.y);
        *(float4*)&Bs[n * TS + ks * 8 + 4] = make_float4(lo.z, hi.z, lo.w, hi.w);
    }
}

// ============================================================================
// Warp-tile MMA: warp owns 32 rows (m0) x 64 cols (n0).
// ============================================================================
__device__ __forceinline__ void mma_tile(float c[2][8][4],
                                         const uint2* A2, const uint2* B2,
                                         int m0, int n0, int gid, int tg) {
    #pragma unroll 1
    for (int ks = 0; ks < 16; ks++) {
        int ko = ks * 4 + tg;
        uint2 aL0 = A2[(m0 + gid) * TS2 + ko];
        uint2 aH0 = A2[(m0 + gid + 8) * TS2 + ko];
        uint2 aL1 = A2[(m0 + gid + 16) * TS2 + ko];
        uint2 aH1 = A2[(m0 + gid + 24) * TS2 + ko];
        uint2 b[8];
        #pragma unroll
        for (int nt = 0; nt < 8; nt++)
            b[nt] = B2[(n0 + nt * 8 + gid) * TS2 + ko];
        #pragma unroll
        for (int nt = 0; nt < 8; nt++) {
            mma_tf32(c[0][nt], aL0.x, aH0.x, aL0.y, aH0.y, b[nt].x, b[nt].y);
            mma_tf32(c[1][nt], aL1.x, aH1.x, aL1.y, aH1.y, b[nt].x, b[nt].y);
        }
    }
}

// ============================================================================
// GEMM 1: g_mh = (h @ W_msg^T) as fp16   (tile 128x128, K=128)
// ============================================================================
__global__ __launch_bounds__(256) void gemm_msg_mma(
    const float* __restrict__ h, int BN)
{
    extern __shared__ float sm[];
    float* As = sm + SM_A_OFF;
    float* Bs = sm + SM_B_OFF;

    int tid = threadIdx.x;
    int lane = tid & 31, warp = tid >> 5;
    int gid = lane >> 2, tg = lane & 3;
    int m0 = (warp >> 1) * 32;
    int n0 = (warp & 1) * 64;
    int row0 = blockIdx.x * 128;

    float c[2][8][4];
    #pragma unroll
    for (int mt = 0; mt < 2; mt++)
        #pragma unroll
        for (int nt = 0; nt < 8; nt++)
            #pragma unroll
            for (int q = 0; q < 4; q++) c[mt][nt][q] = 0.f;

    load_a_tile(As, h, D, row0, BN, tid);
    load_b_tile(Bs, g_Wm, D, 0, tid);
    __syncthreads();

    mma_tile(c, (const uint2*)As, (const uint2*)Bs, m0, n0, gid, tg);

    #pragma unroll
    for (int mt = 0; mt < 2; mt++) {
        int r0 = row0 + m0 + mt * 16 + gid;
        int r1 = r0 + 8;
        #pragma unroll
        for (int nt = 0; nt < 8; nt++) {
            int col = n0 + nt * 8 + tg * 2;
            if (r0 < BN)
                *(__half2*)&g_mh[(long)r0 * D + col] =
                    __floats2half2_rn(c[mt][nt][0], c[mt][nt][1]);
            if (r1 < BN)
                *(__half2*)&g_mh[(long)r1 * D + col] =
                    __floats2half2_rn(c[mt][nt][2], c[mt][nt][3]);
        }
    }
}

// ============================================================================
// GEMM 2: out = LN(h + relu([h|agg] @ W_upd^T + b))   (K=256, 2 phases)
// ============================================================================
__global__ __launch_bounds__(256) void gemm_upd_mma(
    const float* __restrict__ h,
    const float* __restrict__ b_upd, const float* __restrict__ ln_s,
    const float* __restrict__ ln_b, float* __restrict__ out, int BN)
{
    extern __shared__ float sm[];
    float* As = sm + SM_A_OFF;
    float* Bs = sm + SM_B_OFF;

    int tid = threadIdx.x;
    int lane = tid & 31, warp = tid >> 5;
    int gid = lane >> 2, tg = lane & 3;
    int m0 = (warp >> 1) * 32;
    int n0 = (warp & 1) * 64;
    int row0 = blockIdx.x * 128;

    float c[2][8][4];
    #pragma unroll
    for (int mt = 0; mt < 2; mt++)
        #pragma unroll
        for (int nt = 0; nt < 8; nt++)
            #pragma unroll
            for (int q = 0; q < 4; q++) c[mt][nt][q] = 0.f;

    #pragma unroll 1
    for (int phase = 0; phase < 2; phase++) {
        const float* X = (phase == 0) ? h : (const float*)g_agg;
        __syncthreads();                    // prior phase reads complete
        load_a_tile(As, X, D, row0, BN, tid);
        load_b_tile(Bs, g_Wu, 2 * D, phase * D, tid);
        __syncthreads();
        mma_tile(c, (const uint2*)As, (const uint2*)Bs, m0, n0, gid, tg);
    }

    // stage C into As region for per-row epilogue
    __syncthreads();
    #pragma unroll
    for (int mt = 0; mt < 2; mt++) {
        int sr0 = m0 + mt * 16 + gid;
        #pragma unroll
        for (int nt = 0; nt < 8; nt++) {
            int col = n0 + nt * 8 + tg * 2;
            *(float2*)&As[sr0 * TS + col]       = make_float2(c[mt][nt][0], c[mt][nt][1]);
            *(float2*)&As[(sr0 + 8) * TS + col] = make_float2(c[mt][nt][2], c[mt][nt][3]);
        }
    }
    __syncthreads();

    if (tid < 128) {
        int row = row0 + tid;
        if (row < BN) {
            float* Crow = &As[tid * TS];
            float sum = 0.f, ssq = 0.f;
            #pragma unroll 4
            for (int n = 0; n < D; n += 4) {
                float4 cv = *(float4*)&Crow[n];
                float4 bu = __ldg((const float4*)&b_upd[n]);
                float4 hr = *(const float4*)&h[(long)row * D + n];
                float v0 = fmaxf(cv.x + bu.x, 0.f) + hr.x;
                float v1 = fmaxf(cv.y + bu.y, 0.f) + hr.y;
                float v2 = fmaxf(cv.z + bu.z, 0.f) + hr.z;
                float v3 = fmaxf(cv.w + bu.w, 0.f) + hr.w;
                *(float4*)&Crow[n] = make_float4(v0, v1, v2, v3);
                sum += v0 + v1 + v2 + v3;
                ssq += v0 * v0 + v1 * v1 + v2 * v2 + v3 * v3;
            }
            float mean = sum * (1.f / (float)D);
            float var  = ssq * (1.f / (float)D) - mean * mean;
            float rstd = rsqrtf(var + LN_EPS);
            #pragma unroll 4
            for (int n = 0; n < D; n += 4) {
                float4 v  = *(float4*)&Crow[n];
                float4 s4 = __ldg((const float4*)&ln_s[n]);
                float4 b4 = __ldg((const float4*)&ln_b[n]);
                float4 o;
                o.x = (v.x - mean) * rstd * s4.x + b4.x;
                o.y = (v.y - mean) * rstd * s4.y + b4.y;
                o.z = (v.z - mean) * rstd * s4.z + b4.z;
                o.w = (v.w - mean) * rstd * s4.w + b4.w;
                *(float4*)&out[(long)row * D + n] = o;
            }
        }
    }
}

// ---------------------------------------------------------------------------
// Launcher
//  0 h [B*N*D] f32, 1 W_msg [D*D], 2 rel_emb [R*D], 3 W_upd [D*2D],
//  4 b_upd [D], 5 ln_scale [D], 6 ln_bias [D],
//  7 edge_src [E] i32, 8 edge_tgt [E] i32, 9 edge_rel [E] i32, 10 nE scalar
// ---------------------------------------------------------------------------
extern "C" void kernel_launch(void* const* d_in, const int* in_sizes, int n_in,
                              void* d_out, int out_size)
{
    const float* h       = (const float*)d_in[0];
    const float* W_msg   = (const float*)d_in[1];
    const float* rel_emb = (const float*)d_in[2];
    const float* W_upd   = (const float*)d_in[3];
    const float* b_upd   = (const float*)d_in[4];
    const float* ln_s    = (const float*)d_in[5];
    const float* ln_b    = (const float*)d_in[6];
    const int*   e_src   = (const int*)d_in[7];
    const int*   e_tgt   = (const int*)d_in[8];
    const int*   e_rel   = (const int*)d_in[9];
    float* out = (float*)d_out;

    int BN = in_sizes[0] / D;      // 100000
    int N  = BN / BATCH;           // 50000
    int E  = in_sizes[7];          // 800000

    (void)cudaFuncSetAttribute(gemm_msg_mma,
        cudaFuncAttributeMaxDynamicSharedMemorySize, (int)SMEM_MMA);
    (void)cudaFuncSetAttribute(gemm_upd_mma,
        cudaFuncAttributeMaxDynamicSharedMemorySize, (int)SMEM_MMA);

    int nb = (N + SCAN_BLK - 1) / SCAN_BLK;   // 196
    int tiles = (BN + 127) / 128;             // 782

    prep_kernel<<<(N + 255) / 256, 256>>>(W_msg, W_upd, N);
    hist_kernel<<<(E + 255) / 256, 256>>>(e_tgt, E);
    scan1_kernel<<<nb, SCAN_BLK>>>(N);
    scan23_kernel<<<nb, SCAN_BLK>>>(N, E);
    scatter_perm_kernel<<<(E + 255) / 256, 256>>>(e_tgt, E);
    gemm_msg_mma<<<tiles, 256, SMEM_MMA>>>(h, BN);
    gather_kernel<<<(N + 7) / 8, 256>>>(rel_emb, e_src, e_rel, N);
    gemm_upd_mma<<<tiles, 256, SMEM_MMA>>>(h, b_upd, ln_s, ln_b, out, BN);
}

// round 10
// speedup vs baseline: 1.0065x; 1.0065x over previous
#include <cuda_runtime.h>
#include <cstdint>

// Problem constants (dataset-fixed)
#define D 128
#define BATCH 2
#define MAXN 50000
#define MAXBN (BATCH * MAXN)
#define MAXE 800000
#define LN_EPS 1e-5f

// Scratch buffers
__device__ __align__(16) float g_m[MAXBN * D];    // h @ W_msg^T (51MB)
__device__ __align__(16) float g_agg[MAXBN * D];  // gathered aggregate

// CSR-by-target scratch. INVARIANT: g_cnt == 0 at kernel_launch entry
// (zero-initialized at module load; re-zeroed at end of gemm_upd).
__device__ int g_cnt[MAXN];
__device__ int g_excl[MAXN];
__device__ int g_blksum[256];
__device__ int g_rowptr[MAXN + 1];
__device__ int g_cursor[MAXN];
__device__ int g_srcp[MAXE];      // src, permuted by target
__device__ int g_relp[MAXE];      // rel, permuted by target

#define SCAN_BLK 256

// ---- tf32 round-to-nearest (RNA via bit trick) -----------------------------
__device__ __forceinline__ float tf32_rn(float x) {
    uint32_t b = __float_as_uint(x);
    b = (b + 0x00001000u) & 0xFFFFE000u;
    return __uint_as_float(b);
}

// ---- warp-level TF32 MMA (sm_80+ baseline PTX; maps to HMMA) ---------------
__device__ __forceinline__ void mma_tf32(float c[4],
                                         uint32_t a0, uint32_t a1,
                                         uint32_t a2, uint32_t a3,
                                         uint32_t b0, uint32_t b1) {
    asm volatile(
        "mma.sync.aligned.m16n8k8.row.col.f32.tf32.tf32.f32 "
        "{%0,%1,%2,%3}, {%4,%5,%6,%7}, {%8,%9}, {%0,%1,%2,%3};"
        : "+f"(c[0]), "+f"(c[1]), "+f"(c[2]), "+f"(c[3])
        : "r"(a0), "r"(a1), "r"(a2), "r"(a3), "r"(b0), "r"(b1));
}

// smem: A tile [128m][132k-packed] + B tile [128n][132k-packed] floats
// packed layout: word for logical k at pos(k) = (k>>3)*8 + (k&3)*2 + ((k>>2)&1)
// so the (k, k+4) tf32 fragment pair is one aligned 8-byte LDS.
#define TS 132
#define TS2 66
#define SM_A_OFF 0
#define SM_B_OFF (128 * TS)
#define SMEM_MMA ((2 * 128 * TS) * sizeof(float))   // 135168 B

// ============================================================================
// CSR build (histogram -> scan1 -> merged scan23 -> materializing scatter)
// ============================================================================
__global__ void hist_kernel(const int* __restrict__ tgt, int E) {
    int i = blockIdx.x * blockDim.x + threadIdx.x;
    if (i < E) atomicAdd(&g_cnt[tgt[i]], 1);
}

__global__ void scan1_kernel(int N) {
    __shared__ int s[SCAN_BLK];
    int t = threadIdx.x;
    int i = blockIdx.x * SCAN_BLK + t;
    int v = (i < N) ? g_cnt[i] : 0;
    s[t] = v; __syncthreads();
    #pragma unroll
    for (int off = 1; off < SCAN_BLK; off <<= 1) {
        int x = (t >= off) ? s[t - off] : 0;
        __syncthreads();
        s[t] += x; __syncthreads();
    }
    if (i < N) g_excl[i] = s[t] - v;
    if (t == SCAN_BLK - 1) g_blksum[blockIdx.x] = s[t];
}

__global__ void scan23_kernel(int N, int E) {
    __shared__ int s[SCAN_BLK];
    int t = threadIdx.x;
    int b = blockIdx.x;
    s[t] = (t < b) ? g_blksum[t] : 0;
    __syncthreads();
    #pragma unroll
    for (int off = SCAN_BLK / 2; off > 0; off >>= 1) {
        if (t < off) s[t] += s[t + off];
        __syncthreads();
    }
    int offset = s[0];
    int i = b * SCAN_BLK + t;
    if (i < N) {
        int rp = g_excl[i] + offset;
        g_rowptr[i] = rp;
        g_cursor[i] = rp;
    }
    if (b == 0 && t == 0) g_rowptr[N] = E;
}

// scatter: materialize permuted src/rel directly (no perm indirection later)
__global__ void scatter_mat_kernel(const int* __restrict__ tgt,
                                   const int* __restrict__ src,
                                   const int* __restrict__ rel, int E) {
    int i = blockIdx.x * blockDim.x + threadIdx.x;
    if (i < E) {
        int pos = atomicAdd(&g_cursor[tgt[i]], 1);
        g_srcp[pos] = src[i];
        g_relp[pos] = rel[i];
    }
}

// ============================================================================
// Gather: one warp per target node, both batches, no atomics.
// Metadata loads are now direct (srcp/relp), removing one dependency level.
// ============================================================================
__global__ __launch_bounds__(256) void gather_kernel(
    const float* __restrict__ rel_emb, int N)
{
    int w = blockIdx.x * 8 + (threadIdx.x >> 5);
    int lane = threadIdx.x & 31;
    if (w >= N) return;

    int beg = g_rowptr[w];
    int end = g_rowptr[w + 1];

    float4 a0 = make_float4(0.f, 0.f, 0.f, 0.f);
    float4 a1 = make_float4(0.f, 0.f, 0.f, 0.f);

    for (int chunk = beg; chunk < end; chunk += 32) {
        int myE = chunk + lane;
        int ms = 0, mr = 0;
        if (myE < end) {
            ms = __ldg(&g_srcp[myE]);
            mr = __ldg(&g_relp[myE]);
        }
        int cnt = min(32, end - chunk);
        #pragma unroll 4
        for (int j = 0; j < cnt; j++) {
            int s = __shfl_sync(0xFFFFFFFFu, ms, j);
            int r = __shfl_sync(0xFFFFFFFFu, mr, j);
            float4 rv = *(const float4*)&rel_emb[r * D + lane * 4];
            float4 m0 = *(const float4*)&g_m[(long)s * D + lane * 4];
            float4 m1 = *(const float4*)&g_m[((long)N + s) * D + lane * 4];
            a0.x += m0.x * rv.x; a0.y += m0.y * rv.y;
            a0.z += m0.z * rv.z; a0.w += m0.w * rv.w;
            a1.x += m1.x * rv.x; a1.y += m1.y * rv.y;
            a1.z += m1.z * rv.z; a1.w += m1.w * rv.w;
        }
    }

    *(float4*)&g_agg[(long)w * D + lane * 4] = a0;
    *(float4*)&g_agg[((long)N + w) * D + lane * 4] = a1;
}

// ============================================================================
// Tile loaders (packed k-pair layout). Both round to tf32 on the fly.
// ============================================================================
__device__ __forceinline__ void load_a_tile(float* As, const float* __restrict__ X,
                                            int ldx, int row0, int limit, int tid) {
    #pragma unroll
    for (int it = tid; it < 2048; it += 256) {       // 128 rows x 16 ksteps
        int m = it >> 4;
        int ks = it & 15;
        int row = row0 + m;
        float4 lo = make_float4(0.f, 0.f, 0.f, 0.f);
        float4 hi = make_float4(0.f, 0.f, 0.f, 0.f);
        if (row < limit) {
            lo = *(const float4*)&X[(long)row * ldx + ks * 8];
            hi = *(const float4*)&X[(long)row * ldx + ks * 8 + 4];
        }
        float4 p0 = make_float4(tf32_rn(lo.x), tf32_rn(hi.x),
                                tf32_rn(lo.y), tf32_rn(hi.y));
        float4 p1 = make_float4(tf32_rn(lo.z), tf32_rn(hi.z),
                                tf32_rn(lo.w), tf32_rn(hi.w));
        *(float4*)&As[m * TS + ks * 8]     = p0;
        *(float4*)&As[m * TS + ks * 8 + 4] = p1;
    }
}

__device__ __forceinline__ void load_b_tile(float* Bs, const float* __restrict__ W,
                                            int ldw, int koff, int tid) {
    #pragma unroll
    for (int it = tid; it < 2048; it += 256) {
        int n = it >> 4;
        int ks = it & 15;
        float4 lo = *(const float4*)&W[(long)n * ldw + koff + ks * 8];
        float4 hi = *(const float4*)&W[(long)n * ldw + koff + ks * 8 + 4];
        *(float4*)&Bs[n * TS + ks * 8] =
            make_float4(tf32_rn(lo.x), tf32_rn(hi.x), tf32_rn(lo.y), tf32_rn(hi.y));
        *(float4*)&Bs[n * TS + ks * 8 + 4] =
            make_float4(tf32_rn(lo.z), tf32_rn(hi.z), tf32_rn(lo.w), tf32_rn(hi.w));
    }
}

// ============================================================================
// Warp-tile MMA: warp owns 32 rows (m0) x 64 cols (n0).
// ============================================================================
__device__ __forceinline__ void mma_tile(float c[2][8][4],
                                         const uint2* A2, const uint2* B2,
                                         int m0, int n0, int gid, int tg) {
    #pragma unroll 1
    for (int ks = 0; ks < 16; ks++) {
        int ko = ks * 4 + tg;
        uint2 aL0 = A2[(m0 + gid) * TS2 + ko];
        uint2 aH0 = A2[(m0 + gid + 8) * TS2 + ko];
        uint2 aL1 = A2[(m0 + gid + 16) * TS2 + ko];
        uint2 aH1 = A2[(m0 + gid + 24) * TS2 + ko];
        uint2 b[8];
        #pragma unroll
        for (int nt = 0; nt < 8; nt++)
            b[nt] = B2[(n0 + nt * 8 + gid) * TS2 + ko];
        #pragma unroll
        for (int nt = 0; nt < 8; nt++) {
            mma_tf32(c[0][nt], aL0.x, aH0.x, aL0.y, aH0.y, b[nt].x, b[nt].y);
            mma_tf32(c[1][nt], aL1.x, aH1.x, aL1.y, aH1.y, b[nt].x, b[nt].y);
        }
    }
}

// ============================================================================
// GEMM 1: g_m = h @ W_msg^T   (tile 128x128, K=128)
// ============================================================================
__global__ __launch_bounds__(256) void gemm_msg_mma(
    const float* __restrict__ h, const float* __restrict__ Wm, int BN)
{
    extern __shared__ float sm[];
    float* As = sm + SM_A_OFF;
    float* Bs = sm + SM_B_OFF;

    int tid = threadIdx.x;
    int lane = tid & 31, warp = tid >> 5;
    int gid = lane >> 2, tg = lane & 3;
    int m0 = (warp >> 1) * 32;
    int n0 = (warp & 1) * 64;
    int row0 = blockIdx.x * 128;

    float c[2][8][4];
    #pragma unroll
    for (int mt = 0; mt < 2; mt++)
        #pragma unroll
        for (int nt = 0; nt < 8; nt++)
            #pragma unroll
            for (int q = 0; q < 4; q++) c[mt][nt][q] = 0.f;

    load_a_tile(As, h, D, row0, BN, tid);
    load_b_tile(Bs, Wm, D, 0, tid);
    __syncthreads();

    mma_tile(c, (const uint2*)As, (const uint2*)Bs, m0, n0, gid, tg);

    #pragma unroll
    for (int mt = 0; mt < 2; mt++) {
        int r0 = row0 + m0 + mt * 16 + gid;
        int r1 = r0 + 8;
        #pragma unroll
        for (int nt = 0; nt < 8; nt++) {
            int col = n0 + nt * 8 + tg * 2;
            if (r0 < BN)
                *(float2*)&g_m[(long)r0 * D + col] = make_float2(c[mt][nt][0], c[mt][nt][1]);
            if (r1 < BN)
                *(float2*)&g_m[(long)r1 * D + col] = make_float2(c[mt][nt][2], c[mt][nt][3]);
        }
    }
}

// ============================================================================
// GEMM 2: out = LN(h + relu([h|agg] @ W_upd^T + b))   (K=256, 2 phases)
// Also restores the g_cnt==0 invariant for the next replay.
// ============================================================================
__global__ __launch_bounds__(256) void gemm_upd_mma(
    const float* __restrict__ h, const float* __restrict__ Wu,
    const float* __restrict__ b_upd, const float* __restrict__ ln_s,
    const float* __restrict__ ln_b, float* __restrict__ out, int BN)
{
    extern __shared__ float sm[];
    float* As = sm + SM_A_OFF;
    float* Bs = sm + SM_B_OFF;

    int tid = threadIdx.x;

    // restore invariant: g_cnt zeroed for the next graph replay
    for (int i = blockIdx.x * 256 + tid; i < MAXN; i += gridDim.x * 256)
        g_cnt[i] = 0;

    int lane = tid & 31, warp = tid >> 5;
    int gid = lane >> 2, tg = lane & 3;
    int m0 = (warp >> 1) * 32;
    int n0 = (warp & 1) * 64;
    int row0 = blockIdx.x * 128;

    float c[2][8][4];
    #pragma unroll
    for (int mt = 0; mt < 2; mt++)
        #pragma unroll
        for (int nt = 0; nt < 8; nt++)
            #pragma unroll
            for (int q = 0; q < 4; q++) c[mt][nt][q] = 0.f;

    #pragma unroll 1
    for (int phase = 0; phase < 2; phase++) {
        const float* X = (phase == 0) ? h : (const float*)g_agg;
        __syncthreads();                    // prior phase reads complete
        load_a_tile(As, X, D, row0, BN, tid);
        load_b_tile(Bs, Wu, 2 * D, phase * D, tid);
        __syncthreads();
        mma_tile(c, (const uint2*)As, (const uint2*)Bs, m0, n0, gid, tg);
    }

    // stage C into As region for per-row epilogue
    __syncthreads();
    #pragma unroll
    for (int mt = 0; mt < 2; mt++) {
        int sr0 = m0 + mt * 16 + gid;
        #pragma unroll
        for (int nt = 0; nt < 8; nt++) {
            int col = n0 + nt * 8 + tg * 2;
            *(float2*)&As[sr0 * TS + col]       = make_float2(c[mt][nt][0], c[mt][nt][1]);
            *(float2*)&As[(sr0 + 8) * TS + col] = make_float2(c[mt][nt][2], c[mt][nt][3]);
        }
    }
    __syncthreads();

    if (tid < 128) {
        int row = row0 + tid;
        if (row < BN) {
            float* Crow = &As[tid * TS];
            float sum = 0.f, ssq = 0.f;
            #pragma unroll 4
            for (int n = 0; n < D; n += 4) {
                float4 cv = *(float4*)&Crow[n];
                float4 bu = __ldg((const float4*)&b_upd[n]);
                float4 hr = *(const float4*)&h[(long)row * D + n];
                float v0 = fmaxf(cv.x + bu.x, 0.f) + hr.x;
                float v1 = fmaxf(cv.y + bu.y, 0.f) + hr.y;
                float v2 = fmaxf(cv.z + bu.z, 0.f) + hr.z;
                float v3 = fmaxf(cv.w + bu.w, 0.f) + hr.w;
                *(float4*)&Crow[n] = make_float4(v0, v1, v2, v3);
                sum += v0 + v1 + v2 + v3;
                ssq += v0 * v0 + v1 * v1 + v2 * v2 + v3 * v3;
            }
            float mean = sum * (1.f / (float)D);
            float var  = ssq * (1.f / (float)D) - mean * mean;
            float rstd = rsqrtf(var + LN_EPS);
            #pragma unroll 4
            for (int n = 0; n < D; n += 4) {
                float4 v  = *(float4*)&Crow[n];
                float4 s4 = __ldg((const float4*)&ln_s[n]);
                float4 b4 = __ldg((const float4*)&ln_b[n]);
                float4 o;
                o.x = (v.x - mean) * rstd * s4.x + b4.x;
                o.y = (v.y - mean) * rstd * s4.y + b4.y;
                o.z = (v.z - mean) * rstd * s4.z + b4.z;
                o.w = (v.w - mean) * rstd * s4.w + b4.w;
                *(float4*)&out[(long)row * D + n] = o;
            }
        }
    }
}

// ---------------------------------------------------------------------------
// Launcher — forked graph:
//   stream 0 : hist -> scan1 -> scan23 -> scatter_mat ┐
//   stream s2: gemm_msg ───────────────────────────────┤
//   stream 0 : gather -> gemm_upd  (joined via events) ┘
//  Inputs: 0 h, 1 W_msg, 2 rel_emb, 3 W_upd, 4 b_upd, 5 ln_scale, 6 ln_bias,
//          7 edge_src, 8 edge_tgt, 9 edge_rel, 10 nE
// ---------------------------------------------------------------------------
extern "C" void kernel_launch(void* const* d_in, const int* in_sizes, int n_in,
                              void* d_out, int out_size)
{
    const float* h       = (const float*)d_in[0];
    const float* W_msg   = (const float*)d_in[1];
    const float* rel_emb = (const float*)d_in[2];
    const float* W_upd   = (const float*)d_in[3];
    const float* b_upd   = (const float*)d_in[4];
    const float* ln_s    = (const float*)d_in[5];
    const float* ln_b    = (const float*)d_in[6];
    const int*   e_src   = (const int*)d_in[7];
    const int*   e_tgt   = (const int*)d_in[8];
    const int*   e_rel   = (const int*)d_in[9];
    float* out = (float*)d_out;

    int BN = in_sizes[0] / D;      // 100000
    int N  = BN / BATCH;           // 50000
    int E  = in_sizes[7];          // 800000

    // one-time setup on the (uncaptured) correctness call
    static cudaStream_t s2 = 0;
    static cudaEvent_t ev_fork = 0, ev_join = 0;
    static bool ready = false;
    if (!ready) {
        cudaStreamCreateWithFlags(&s2, cudaStreamNonBlocking);
        cudaEventCreateWithFlags(&ev_fork, cudaEventDisableTiming);
        cudaEventCreateWithFlags(&ev_join, cudaEventDisableTiming);
        (void)cudaFuncSetAttribute(gemm_msg_mma,
            cudaFuncAttributeMaxDynamicSharedMemorySize, (int)SMEM_MMA);
        (void)cudaFuncSetAttribute(gemm_upd_mma,
            cudaFuncAttributeMaxDynamicSharedMemorySize, (int)SMEM_MMA);
        ready = true;
    }

    int nb = (N + SCAN_BLK - 1) / SCAN_BLK;   // 196
    int tiles = (BN + 127) / 128;             // 782

    // fork point
    cudaEventRecord(ev_fork, 0);

    // branch B (side stream): message GEMM
    cudaStreamWaitEvent(s2, ev_fork, 0);
    gemm_msg_mma<<<tiles, 256, SMEM_MMA, s2>>>(h, W_msg, BN);
    cudaEventRecord(ev_join, s2);

    // branch A (main stream): CSR build
    hist_kernel<<<(E + 255) / 256, 256>>>(e_tgt, E);
    scan1_kernel<<<nb, SCAN_BLK>>>(N);
    scan23_kernel<<<nb, SCAN_BLK>>>(N, E);
    scatter_mat_kernel<<<(E + 255) / 256, 256>>>(e_tgt, e_src, e_rel, E);

    // join, then gather + update
    cudaStreamWaitEvent(0, ev_join, 0);
    gather_kernel<<<(N + 7) / 8, 256>>>(rel_emb, N);
    gemm_upd_mma<<<tiles, 256, SMEM_MMA>>>(h, W_upd, b_upd, ln_s, ln_b, out, BN);
}

// round 12
// speedup vs baseline: 1.3575x; 1.3487x over previous
#include <cuda_runtime.h>
#include <cuda_fp16.h>
#include <cstdint>

// Problem constants (dataset-fixed)
#define D 128
#define BATCH 2
#define MAXN 50000
#define MAXBN (BATCH * MAXN)
#define MAXE 800000
#define LN_EPS 1e-5f

// Scratch buffers
__device__ __align__(16) float g_m[MAXBN * D];    // h @ W_msg^T (51MB)
__device__ __align__(16) float g_agg[MAXBN * D];  // gathered aggregate

// CSR-by-target scratch. INVARIANT: g_cnt == 0 at kernel_launch entry
// (zero-initialized at module load; re-zeroed at end of gemm_upd).
__device__ int g_cnt[MAXN];
__device__ int g_excl[MAXN];
__device__ int g_blksum[256];
__device__ int g_rowptr[MAXN + 1];
__device__ int g_cursor[MAXN];
__device__ int g_srcp[MAXE];      // src, permuted by target
__device__ int g_relp[MAXE];      // rel, permuted by target

#define SCAN_BLK 256

// ---- warp-level FP16 MMA (sm_80+ baseline PTX) -----------------------------
__device__ __forceinline__ void mma_f16(float c[4],
                                        uint32_t a0, uint32_t a1,
                                        uint32_t a2, uint32_t a3,
                                        uint32_t b0, uint32_t b1) {
    asm volatile(
        "mma.sync.aligned.m16n8k16.row.col.f32.f16.f16.f32 "
        "{%0,%1,%2,%3}, {%4,%5,%6,%7}, {%8,%9}, {%0,%1,%2,%3};"
        : "+f"(c[0]), "+f"(c[1]), "+f"(c[2]), "+f"(c[3])
        : "r"(a0), "r"(a1), "r"(a2), "r"(a3), "r"(b0), "r"(b1));
}

// smem tiles: A [128m][HS half2] + B [128n][HS half2], packed so that the
// (k-lo, k-hi) fragment word pair of each m16n8k16 step is one aligned LDS.64.
// Within kstep ks, half2 word for logical pair q (q = (k%16)/2) sits at
// slot: q<4 -> 2q ; q>=4 -> 2(q-4)+1. Thread tg reads slots 2tg,2tg+1.
#define HS 68                       // half2 stride per row (272 B, 16B mult)
#define HS2 34                      // uint2 stride
#define SMEM_MMA (2 * 128 * HS * sizeof(__half2))   // 69632 B
// upd epilogue stages C as f32 rows of stride 132 over the SAME smem:
// 128*132*4 = 67584 <= 69632.
#define CTS 132

// ============================================================================
// CSR build (histogram -> scan1 -> merged scan23 -> materializing scatter)
// ============================================================================
__global__ void hist_kernel(const int* __restrict__ tgt, int E) {
    int i = blockIdx.x * blockDim.x + threadIdx.x;
    if (i < E) atomicAdd(&g_cnt[tgt[i]], 1);
}

__global__ void scan1_kernel(int N) {
    __shared__ int s[SCAN_BLK];
    int t = threadIdx.x;
    int i = blockIdx.x * SCAN_BLK + t;
    int v = (i < N) ? g_cnt[i] : 0;
    s[t] = v; __syncthreads();
    #pragma unroll
    for (int off = 1; off < SCAN_BLK; off <<= 1) {
        int x = (t >= off) ? s[t - off] : 0;
        __syncthreads();
        s[t] += x; __syncthreads();
    }
    if (i < N) g_excl[i] = s[t] - v;
    if (t == SCAN_BLK - 1) g_blksum[blockIdx.x] = s[t];
}

__global__ void scan23_kernel(int N, int E) {
    __shared__ int s[SCAN_BLK];
    int t = threadIdx.x;
    int b = blockIdx.x;
    s[t] = (t < b) ? g_blksum[t] : 0;
    __syncthreads();
    #pragma unroll
    for (int off = SCAN_BLK / 2; off > 0; off >>= 1) {
        if (t < off) s[t] += s[t + off];
        __syncthreads();
    }
    int offset = s[0];
    int i = b * SCAN_BLK + t;
    if (i < N) {
        int rp = g_excl[i] + offset;
        g_rowptr[i] = rp;
        g_cursor[i] = rp;
    }
    if (b == 0 && t == 0) g_rowptr[N] = E;
}

__global__ void scatter_mat_kernel(const int* __restrict__ tgt,
                                   const int* __restrict__ src,
                                   const int* __restrict__ rel, int E) {
    int i = blockIdx.x * blockDim.x + threadIdx.x;
    if (i < E) {
        int pos = atomicAdd(&g_cursor[tgt[i]], 1);
        g_srcp[pos] = src[i];
        g_relp[pos] = rel[i];
    }
}

// ============================================================================
// Gather: one warp per target node, both batches, no atomics
// ============================================================================
__global__ __launch_bounds__(256) void gather_kernel(
    const float* __restrict__ rel_emb, int N)
{
    int w = blockIdx.x * 8 + (threadIdx.x >> 5);
    int lane = threadIdx.x & 31;
    if (w >= N) return;

    int beg = g_rowptr[w];
    int end = g_rowptr[w + 1];

    float4 a0 = make_float4(0.f, 0.f, 0.f, 0.f);
    float4 a1 = make_float4(0.f, 0.f, 0.f, 0.f);

    for (int chunk = beg; chunk < end; chunk += 32) {
        int myE = chunk + lane;
        int ms = 0, mr = 0;
        if (myE < end) {
            ms = __ldg(&g_srcp[myE]);
            mr = __ldg(&g_relp[myE]);
        }
        int cnt = min(32, end - chunk);
        #pragma unroll 4
        for (int j = 0; j < cnt; j++) {
            int s = __shfl_sync(0xFFFFFFFFu, ms, j);
            int r = __shfl_sync(0xFFFFFFFFu, mr, j);
            float4 rv = *(const float4*)&rel_emb[r * D + lane * 4];
            float4 m0 = *(const float4*)&g_m[(long)s * D + lane * 4];
            float4 m1 = *(const float4*)&g_m[((long)N + s) * D + lane * 4];
            a0.x += m0.x * rv.x; a0.y += m0.y * rv.y;
            a0.z += m0.z * rv.z; a0.w += m0.w * rv.w;
            a1.x += m1.x * rv.x; a1.y += m1.y * rv.y;
            a1.z += m1.z * rv.z; a1.w += m1.w * rv.w;
        }
    }

    *(float4*)&g_agg[(long)w * D + lane * 4] = a0;
    *(float4*)&g_agg[((long)N + w) * D + lane * 4] = a1;
}

// ============================================================================
// Tile loaders: f32 gmem -> packed fp16 smem. One (row, kstep) per iteration:
// 16 floats -> 8 half2 stored interleaved [q0,q4,q1,q5,q2,q6,q3,q7].
// ============================================================================
__device__ __forceinline__ uint32_t f2h2(float a, float b) {
    __half2 v = __floats2half2_rn(a, b);
    return *(uint32_t*)&v;
}

__device__ __forceinline__ void load_tile_f16(uint32_t* Ts,
                                              const float* __restrict__ X,
                                              int ldx, int row0, int limit,
                                              int koff, int tid) {
    #pragma unroll
    for (int it = tid; it < 1024; it += 256) {       // 128 rows x 8 ksteps
        int m = it >> 3;
        int ks = it & 7;
        int row = row0 + m;
        float4 x0 = make_float4(0.f, 0.f, 0.f, 0.f);
        float4 x1 = x0, x2 = x0, x3 = x0;
        if (row < limit) {
            const float* p = &X[(long)row * ldx + koff + ks * 16];
            x0 = *(const float4*)(p);
            x1 = *(const float4*)(p + 4);
            x2 = *(const float4*)(p + 8);
            x3 = *(const float4*)(p + 12);
        }
        // logical half2 pairs q0..q7 = (k0k1),(k2k3)...(k14k15)
        uint32_t q0 = f2h2(x0.x, x0.y), q1 = f2h2(x0.z, x0.w);
        uint32_t q2 = f2h2(x1.x, x1.y), q3 = f2h2(x1.z, x1.w);
        uint32_t q4 = f2h2(x2.x, x2.y), q5 = f2h2(x2.z, x2.w);
        uint32_t q6 = f2h2(x3.x, x3.y), q7 = f2h2(x3.z, x3.w);
        uint32_t* dst = Ts + m * HS + ks * 8;
        *(uint4*)(dst)     = make_uint4(q0, q4, q1, q5);
        *(uint4*)(dst + 4) = make_uint4(q2, q6, q3, q7);
    }
}

// ============================================================================
// Warp-tile MMA: warp owns 32 rows (m0) x 64 cols (n0); 8 ksteps of k16.
// ============================================================================
__device__ __forceinline__ void mma_tile(float c[2][8][4],
                                         const uint2* A2, const uint2* B2,
                                         int m0, int n0, int gid, int tg) {
    #pragma unroll 1
    for (int ks = 0; ks < 8; ks++) {
        int ko = ks * 4 + tg;
        uint2 aL0 = A2[(m0 + gid) * HS2 + ko];        // {a0, a2} rows m0+gid
        uint2 aH0 = A2[(m0 + gid + 8) * HS2 + ko];    // {a1, a3}
        uint2 aL1 = A2[(m0 + gid + 16) * HS2 + ko];
        uint2 aH1 = A2[(m0 + gid + 24) * HS2 + ko];
        uint2 b[8];
        #pragma unroll
        for (int nt = 0; nt < 8; nt++)
            b[nt] = B2[(n0 + nt * 8 + gid) * HS2 + ko];
        #pragma unroll
        for (int nt = 0; nt < 8; nt++) {
            mma_f16(c[0][nt], aL0.x, aH0.x, aL0.y, aH0.y, b[nt].x, b[nt].y);
            mma_f16(c[1][nt], aL1.x, aH1.x, aL1.y, aH1.y, b[nt].x, b[nt].y);
        }
    }
}

// ============================================================================
// GEMM 1: g_m = h @ W_msg^T   (tile 128x128, K=128)
// ============================================================================
__global__ __launch_bounds__(256) void gemm_msg_mma(
    const float* __restrict__ h, const float* __restrict__ Wm, int BN)
{
    extern __shared__ uint32_t smu[];
    uint32_t* As = smu;
    uint32_t* Bs = smu + 128 * HS;

    int tid = threadIdx.x;
    int lane = tid & 31, warp = tid >> 5;
    int gid = lane >> 2, tg = lane & 3;
    int m0 = (warp >> 1) * 32;
    int n0 = (warp & 1) * 64;
    int row0 = blockIdx.x * 128;

    float c[2][8][4];
    #pragma unroll
    for (int mt = 0; mt < 2; mt++)
        #pragma unroll
        for (int nt = 0; nt < 8; nt++)
            #pragma unroll
            for (int q = 0; q < 4; q++) c[mt][nt][q] = 0.f;

    load_tile_f16(As, h, D, row0, BN, 0, tid);
    load_tile_f16(Bs, Wm, D, 0, 128, 0, tid);   // 128 weight rows, no oob
    __syncthreads();

    mma_tile(c, (const uint2*)As, (const uint2*)Bs, m0, n0, gid, tg);

    #pragma unroll
    for (int mt = 0; mt < 2; mt++) {
        int r0 = row0 + m0 + mt * 16 + gid;
        int r1 = r0 + 8;
        #pragma unroll
        for (int nt = 0; nt < 8; nt++) {
            int col = n0 + nt * 8 + tg * 2;
            if (r0 < BN)
                *(float2*)&g_m[(long)r0 * D + col] = make_float2(c[mt][nt][0], c[mt][nt][1]);
            if (r1 < BN)
                *(float2*)&g_m[(long)r1 * D + col] = make_float2(c[mt][nt][2], c[mt][nt][3]);
        }
    }
}

// ============================================================================
// GEMM 2: out = LN(h + relu([h|agg] @ W_upd^T + b))   (K=256, 2 phases)
// Also restores the g_cnt==0 invariant for the next replay.
// ============================================================================
__global__ __launch_bounds__(256) void gemm_upd_mma(
    const float* __restrict__ h, const float* __restrict__ Wu,
    const float* __restrict__ b_upd, const float* __restrict__ ln_s,
    const float* __restrict__ ln_b, float* __restrict__ out, int BN)
{
    extern __shared__ uint32_t smu[];
    uint32_t* As = smu;
    uint32_t* Bs = smu + 128 * HS;
    float* Cs = (float*)smu;                 // f32 staging, stride CTS

    int tid = threadIdx.x;

    // restore invariant: g_cnt zeroed for the next graph replay
    for (int i = blockIdx.x * 256 + tid; i < MAXN; i += gridDim.x * 256)
        g_cnt[i] = 0;

    int lane = tid & 31, warp = tid >> 5;
    int gid = lane >> 2, tg = lane & 3;
    int m0 = (warp >> 1) * 32;
    int n0 = (warp & 1) * 64;
    int row0 = blockIdx.x * 128;

    float c[2][8][4];
    #pragma unroll
    for (int mt = 0; mt < 2; mt++)
        #pragma unroll
        for (int nt = 0; nt < 8; nt++)
            #pragma unroll
            for (int q = 0; q < 4; q++) c[mt][nt][q] = 0.f;

    #pragma unroll 1
    for (int phase = 0; phase < 2; phase++) {
        const float* X = (phase == 0) ? h : (const float*)g_agg;
        __syncthreads();                    // prior phase reads complete
        load_tile_f16(As, X, D, row0, BN, 0, tid);
        load_tile_f16(Bs, Wu, 2 * D, 0, 128, phase * D, tid);
        __syncthreads();
        mma_tile(c, (const uint2*)As, (const uint2*)Bs, m0, n0, gid, tg);
    }

    // stage C (f32) over the tile buffers for per-row epilogue
    __syncthreads();
    #pragma unroll
    for (int mt = 0; mt < 2; mt++) {
        int sr0 = m0 + mt * 16 + gid;
        #pragma unroll
        for (int nt = 0; nt < 8; nt++) {
            int col = n0 + nt * 8 + tg * 2;
            *(float2*)&Cs[sr0 * CTS + col]       = make_float2(c[mt][nt][0], c[mt][nt][1]);
            *(float2*)&Cs[(sr0 + 8) * CTS + col] = make_float2(c[mt][nt][2], c[mt][nt][3]);
        }
    }
    __syncthreads();

    if (tid < 128) {
        int row = row0 + tid;
        if (row < BN) {
            float* Crow = &Cs[tid * CTS];
            float sum = 0.f, ssq = 0.f;
            #pragma unroll 4
            for (int n = 0; n < D; n += 4) {
                float4 cv = *(float4*)&Crow[n];
                float4 bu = __ldg((const float4*)&b_upd[n]);
                float4 hr = *(const float4*)&h[(long)row * D + n];
                float v0 = fmaxf(cv.x + bu.x, 0.f) + hr.x;
                float v1 = fmaxf(cv.y + bu.y, 0.f) + hr.y;
                float v2 = fmaxf(cv.z + bu.z, 0.f) + hr.z;
                float v3 = fmaxf(cv.w + bu.w, 0.f) + hr.w;
                *(float4*)&Crow[n] = make_float4(v0, v1, v2, v3);
                sum += v0 + v1 + v2 + v3;
                ssq += v0 * v0 + v1 * v1 + v2 * v2 + v3 * v3;
            }
            float mean = sum * (1.f / (float)D);
            float var  = ssq * (1.f / (float)D) - mean * mean;
            float rstd = rsqrtf(var + LN_EPS);
            #pragma unroll 4
            for (int n = 0; n < D; n += 4) {
                float4 v  = *(float4*)&Crow[n];
                float4 s4 = __ldg((const float4*)&ln_s[n]);
                float4 b4 = __ldg((const float4*)&ln_b[n]);
                float4 o;
                o.x = (v.x - mean) * rstd * s4.x + b4.x;
                o.y = (v.y - mean) * rstd * s4.y + b4.y;
                o.z = (v.z - mean) * rstd * s4.z + b4.z;
                o.w = (v.w - mean) * rstd * s4.w + b4.w;
                *(float4*)&out[(long)row * D + n] = o;
            }
        }
    }
}

// ---------------------------------------------------------------------------
// Launcher — forked graph:
//   stream 0 : hist -> scan1 -> scan23 -> scatter_mat ┐
//   stream s2: gemm_msg ───────────────────────────────┤
//   stream 0 : gather -> gemm_upd  (joined via events) ┘
//  Inputs: 0 h, 1 W_msg, 2 rel_emb, 3 W_upd, 4 b_upd, 5 ln_scale, 6 ln_bias,
//          7 edge_src, 8 edge_tgt, 9 edge_rel, 10 nE
// ---------------------------------------------------------------------------
extern "C" void kernel_launch(void* const* d_in, const int* in_sizes, int n_in,
                              void* d_out, int out_size)
{
    const float* h       = (const float*)d_in[0];
    const float* W_msg   = (const float*)d_in[1];
    const float* rel_emb = (const float*)d_in[2];
    const float* W_upd   = (const float*)d_in[3];
    const float* b_upd   = (const float*)d_in[4];
    const float* ln_s    = (const float*)d_in[5];
    const float* ln_b    = (const float*)d_in[6];
    const int*   e_src   = (const int*)d_in[7];
    const int*   e_tgt   = (const int*)d_in[8];
    const int*   e_rel   = (const int*)d_in[9];
    float* out = (float*)d_out;

    int BN = in_sizes[0] / D;      // 100000
    int N  = BN / BATCH;           // 50000
    int E  = in_sizes[7];          // 800000

    // one-time setup on the (uncaptured) correctness call
    static cudaStream_t s2 = 0;
    static cudaEvent_t ev_fork = 0, ev_join = 0;
    static bool ready = false;
    if (!ready) {
        cudaStreamCreateWithFlags(&s2, cudaStreamNonBlocking);
        cudaEventCreateWithFlags(&ev_fork, cudaEventDisableTiming);
        cudaEventCreateWithFlags(&ev_join, cudaEventDisableTiming);
        (void)cudaFuncSetAttribute(gemm_msg_mma,
            cudaFuncAttributeMaxDynamicSharedMemorySize, (int)SMEM_MMA);
        (void)cudaFuncSetAttribute(gemm_upd_mma,
            cudaFuncAttributeMaxDynamicSharedMemorySize, (int)SMEM_MMA);
        ready = true;
    }

    int nb = (N + SCAN_BLK - 1) / SCAN_BLK;   // 196
    int tiles = (BN + 127) / 128;             // 782

    // fork point
    cudaEventRecord(ev_fork, 0);

    // branch B (side stream): message GEMM
    cudaStreamWaitEvent(s2, ev_fork, 0);
    gemm_msg_mma<<<tiles, 256, SMEM_MMA, s2>>>(h, W_msg, BN);
    cudaEventRecord(ev_join, s2);

    // branch A (main stream): CSR build
    hist_kernel<<<(E + 255) / 256, 256>>>(e_tgt, E);
    scan1_kernel<<<nb, SCAN_BLK>>>(N);
    scan23_kernel<<<nb, SCAN_BLK>>>(N, E);
    scatter_mat_kernel<<<(E + 255) / 256, 256>>>(e_tgt, e_src, e_rel, E);

    // join, then gather + update
    cudaStreamWaitEvent(0, ev_join, 0);
    gather_kernel<<<(N + 7) / 8, 256>>>(rel_emb, N);
    gemm_upd_mma<<<tiles, 256, SMEM_MMA>>>(h, W_upd, b_upd, ln_s, ln_b, out, BN);
}